// round 11
// baseline (speedup 1.0000x reference)
#include <cuda_runtime.h>
#include <cuda_bf16.h>
#include <cstdint>

// Problem constants
#define B_    4
#define C_    256
#define H_    64
#define W_    64
#define O_    256
#define KK_   9
#define HW_   4096
#define NPIX  16384
#define KTOT  2304
#define OMCH  27
#define OMSZ  (B_*OMCH*HW_)   // 442368

// GEMM chunking: k' = kk*256 + c; 72 chunks of 32 channels
#define NCH   72
#define KPAD  40              // padded K row -> 80B rows, conflict-free ldmatrix/STS.128

// Device scratch
__device__ float  g_om[OMSZ];
// main GEMM weights: per chunk [hi 256x40 bf16][lo 256x40 bf16] = 40960 B
__device__ float4 g_wA[NCH * 2560];
// offset-conv weights: per chunk [hi 32x40 bf16][lo 32x40 bf16] = 5120 B
__device__ __nv_bfloat16 g_wOff[NCH * 2560];

// ---------------------------------------------------------------------------
// PTX helpers
// ---------------------------------------------------------------------------
__device__ __forceinline__ uint32_t s2u(const void* p) {
    uint32_t r;
    asm("{ .reg .u64 t; cvta.to.shared.u64 t, %1; cvt.u32.u64 %0, t; }" : "=r"(r) : "l"(p));
    return r;
}
__device__ __forceinline__ void ldsm4(uint32_t* r, uint32_t addr) {
    asm volatile("ldmatrix.sync.aligned.m8n8.x4.shared.b16 {%0,%1,%2,%3}, [%4];"
                 : "=r"(r[0]), "=r"(r[1]), "=r"(r[2]), "=r"(r[3]) : "r"(addr));
}
__device__ __forceinline__ void mma_bf16(float* d, const uint32_t* a, const uint32_t* b) {
    asm volatile(
        "mma.sync.aligned.m16n8k16.row.col.f32.bf16.bf16.f32 "
        "{%0,%1,%2,%3}, {%4,%5,%6,%7}, {%8,%9}, {%0,%1,%2,%3};"
        : "+f"(d[0]), "+f"(d[1]), "+f"(d[2]), "+f"(d[3])
        : "r"(a[0]), "r"(a[1]), "r"(a[2]), "r"(a[3]), "r"(b[0]), "r"(b[1]));
}
__device__ __forceinline__ void cp_async16(uint32_t dst, const void* src) {
    asm volatile("cp.async.cg.shared.global [%0], [%1], 16;" :: "r"(dst), "l"(src));
}
__device__ __forceinline__ void cp_commit() {
    asm volatile("cp.async.commit_group;" ::: "memory");
}
__device__ __forceinline__ void cp_wait0() {
    asm volatile("cp.async.wait_group 0;" ::: "memory");
}
__device__ __forceinline__ void pack4(const float* v, uint32_t* ph, uint32_t* pl) {
#pragma unroll
    for (int q = 0; q < 4; q++) {
        uint32_t ua = __float_as_uint(v[2 * q]);
        uint32_t ub = __float_as_uint(v[2 * q + 1]);
        float ta = __uint_as_float(ua & 0xffff0000u);
        float tb = __uint_as_float(ub & 0xffff0000u);
        ph[q] = __byte_perm(ua, ub, 0x7632);
        pl[q] = __byte_perm(__float_as_uint(v[2 * q] - ta),
                            __float_as_uint(v[2 * q + 1] - tb), 0x7632);
    }
}

// ---------------------------------------------------------------------------
// SMEM layout (main kernel, per CTA): A ring x2 (full M=256), B ring x2 (64 px),
// params for 9 kk x 64 px. 113920 B -> two CTAs per SM.
// ---------------------------------------------------------------------------
#define SM_A     0        // 2 x 40960
#define SM_B     81920    // 2 x 10240 (hi 5120 + lo 5120)
#define SM_IDXA  102400   // 576 u32 (idx00|flag<<12|idx01<<16)
#define SM_WQ    104704   // 576 float4
#define DYN_SMEM 113920

// om kernel smem: A 2x5120, B 2x20480
#define OM_A     0
#define OM_B     10240
#define OM_SMEM  51200

// ---------------------------------------------------------------------------
// Kernel 1a: pack main weights into bf16 hi/lo padded tiles
// ---------------------------------------------------------------------------
__global__ void prep_w_kernel(const float* __restrict__ weight) {
    int i = blockIdx.x * 256 + threadIdx.x;   // 0 .. 589823
    int chunk = i >> 13;
    int rem   = i & 8191;
    int o     = rem >> 5;
    int kl    = rem & 31;
    int kk = chunk >> 3;
    int cg = chunk & 7;
    int c  = cg * 32 + kl;
    float w = weight[o * KTOT + c * 9 + kk];
    __nv_bfloat16 hi = __float2bfloat16(w);
    __nv_bfloat16 lo = __float2bfloat16(w - __bfloat162float(hi));
    __nv_bfloat16* base = (__nv_bfloat16*)g_wA + (size_t)chunk * 20480;
    base[o * KPAD + kl]         = hi;
    base[10240 + o * KPAD + kl] = lo;
}

// ---------------------------------------------------------------------------
// Kernel 1b: pack offset-conv weights (27 rows, padded to 32) per chunk
// ---------------------------------------------------------------------------
__global__ void prep_woff_kernel(const float* __restrict__ w_off) {
    int i = blockIdx.x * 256 + threadIdx.x;   // 0 .. 73727
    int chunk = i >> 10;
    int rem   = i & 1023;
    int j     = rem >> 5;
    int kl    = rem & 31;
    int kk = chunk >> 3;
    int cg = chunk & 7;
    float w = (j < OMCH) ? w_off[j * KTOT + (cg * 32 + kl) * 9 + kk] : 0.f;
    __nv_bfloat16 hi = __float2bfloat16(w);
    __nv_bfloat16 lo = __float2bfloat16(w - __bfloat162float(hi));
    __nv_bfloat16* base = g_wOff + (size_t)chunk * 2560;
    base[j * KPAD + kl]        = hi;
    base[1280 + j * KPAD + kl] = lo;
}

// ---------------------------------------------------------------------------
// Kernel 2: offset conv as tensor GEMM (unchanged R9).
// ---------------------------------------------------------------------------
__global__ __launch_bounds__(256, 1) void om_mma_kernel(
    const float* __restrict__ x, const float* __restrict__ bo)
{
    extern __shared__ char smem[];
    uint32_t sb = s2u(smem);

    const int t    = threadIdx.x;
    const int lane = t & 31;
    const int nw   = t >> 5;
    const int pbase = blockIdx.x * 128;
    const int b     = pbase >> 12;
    const int pib   = pbase & 4095;
    const int nloc  = t & 127;
    const int klq   = t >> 7;
    const int ph_   = (pib + nloc) >> 6;
    const int pw_   = (pib + nloc) & 63;

    const float* xb = x + ((size_t)b << 20);

    float acc[2][2][4];
#pragma unroll
    for (int i = 0; i < 2; i++)
#pragma unroll
        for (int j = 0; j < 2; j++)
#pragma unroll
            for (int q = 0; q < 4; q++) acc[i][j][q] = 0.f;

    const uint32_t a_off = (uint32_t)((lane & 15) * 80 + ((lane >> 4) << 4));
    const uint32_t b_off = (uint32_t)((((lane >> 4) << 3) + (lane & 7)) * 80
                                      + (((lane >> 3) & 1) << 4));
    const uint32_t bstore = (uint32_t)(nloc * 80 + klq * 32);

    auto buildB = [&](int c, float* v) {
        int kk = c >> 3, cg = c & 7;
        int kh = kk / 3, kw = kk - 3 * kh;
        int y  = ph_ + kh - 1;
        int xx = pw_ + kw - 1;
        bool ok = ((unsigned)y < 64u) && ((unsigned)xx < 64u);
        const float* xc = xb + ((size_t)(cg * 32 + klq * 16) << 12) + (y << 6) + xx;
#pragma unroll
        for (int j = 0; j < 16; j++)
            v[j] = ok ? __ldg(xc + ((size_t)j << 12)) : 0.f;
    };

    uint32_t ph[8], pl[8];

    {
        for (int r = 0; r < 2; r++) {
            int idx = t + (r << 8);
            if (idx < 320)
                cp_async16(sb + OM_A + (uint32_t)(idx << 4), (const char*)g_wOff + (idx << 4));
        }
        cp_commit();
        float v[16];
        buildB(0, v);
        pack4(v, ph, pl);
        pack4(v + 8, ph + 4, pl + 4);
    }

    for (int c = 0; c < NCH; c++) {
        const int buf = c & 1;

        {
            char* bh = smem + OM_B + buf * 20480 + bstore;
            *(float4*)bh                = *(float4*)(ph + 0);
            *(float4*)(bh + 16)         = *(float4*)(ph + 4);
            *(float4*)(bh + 10240)      = *(float4*)(pl + 0);
            *(float4*)(bh + 10240 + 16) = *(float4*)(pl + 4);
        }
        cp_wait0();
        __syncthreads();

        const bool pf = (c + 1 < NCH);
        if (pf) {
            const char* srcA = (const char*)(g_wOff + (size_t)(c + 1) * 2560);
            uint32_t dA = sb + OM_A + (buf ^ 1) * 5120;
            for (int r = 0; r < 2; r++) {
                int idx = t + (r << 8);
                if (idx < 320)
                    cp_async16(dA + (uint32_t)(idx << 4), srcA + (idx << 4));
            }
            cp_commit();
        }

        float v[16];
        if (pf) buildB(c + 1, v);

        const uint32_t A0 = sb + OM_A + buf * 5120;
        const uint32_t B0 = sb + OM_B + buf * 20480;
#pragma unroll
        for (int pass = 0; pass < 3; pass++) {
            uint32_t Ab = A0 + (pass == 2 ? 2560u : 0u);
            uint32_t Bb = B0 + (pass == 1 ? 10240u : 0u);
#pragma unroll
            for (int h = 0; h < 2; h++) {
                uint32_t af[2][4], bfr[4];
#pragma unroll
                for (int mi = 0; mi < 2; mi++)
                    ldsm4(af[mi], Ab + a_off + (uint32_t)((mi * 16) * 80 + h * 32));
                ldsm4(bfr, Bb + b_off + (uint32_t)((nw * 16) * 80 + h * 32));
#pragma unroll
                for (int mi = 0; mi < 2; mi++) {
                    mma_bf16(acc[mi][0], af[mi], &bfr[0]);
                    mma_bf16(acc[mi][1], af[mi], &bfr[2]);
                }
            }
        }
        if (pf) {
            pack4(v, ph, pl);
            pack4(v + 8, ph + 4, pl + 4);
        }
    }

#pragma unroll
    for (int mi = 0; mi < 2; mi++) {
#pragma unroll
        for (int half = 0; half < 2; half++) {
            int j = mi * 16 + (lane >> 2) + half * 8;
            if (j < OMCH) {
                float bv = __ldg(bo + j);
                float* row = g_om + (((size_t)(b * OMCH + j)) << 12) + pib;
#pragma unroll
                for (int nj = 0; nj < 2; nj++) {
                    int cc = nw * 16 + nj * 8 + ((lane & 3) << 1);
                    row[cc]     = acc[mi][nj][2 * half]     + bv;
                    row[cc + 1] = acc[mi][nj][2 * half + 1] + bv;
                }
            }
        }
    }
}

// ---------------------------------------------------------------------------
// Kernel 3: fused bilinear-sample + bf16 3-pass mma.sync GEMM.
// grid = 256 CTAs (64-pixel tiles) x 256 threads = 8 warps; TWO CTAs per SM
// (launch_bounds(256,2)) so barriers/latency of one CTA hide under the other.
// Warp grid 4 M x 2 N, warp tile 64x32 (identical per-warp code to R10).
// Per h-phase fragment reuse: Ah,Bh -> AhBh; Bl -> AhBl; Al -> AlBh.
// ---------------------------------------------------------------------------
struct GatherCtx {
    int i00, i01, i10, i11;
    float4 wq;
    const float* xch;
};

__device__ __forceinline__ void gather_issue(const GatherCtx& g, int grp, float* r) {
    const float* xc0 = g.xch + ((size_t)(2 * grp) << 12);
    const float* xc1 = xc0 + 4096;
    r[0] = __ldg(xc0 + g.i00); r[1] = __ldg(xc0 + g.i01);
    r[2] = __ldg(xc0 + g.i10); r[3] = __ldg(xc0 + g.i11);
    r[4] = __ldg(xc1 + g.i00); r[5] = __ldg(xc1 + g.i01);
    r[6] = __ldg(xc1 + g.i10); r[7] = __ldg(xc1 + g.i11);
}
__device__ __forceinline__ void gather_combine(const GatherCtx& g, const float* r,
                                               float& v0, float& v1) {
    v0 = g.wq.x * r[0] + g.wq.y * r[1] + g.wq.z * r[2] + g.wq.w * r[3];
    v1 = g.wq.x * r[4] + g.wq.y * r[5] + g.wq.z * r[6] + g.wq.w * r[7];
}

__global__ __launch_bounds__(256, 2) void dcn_mma_kernel(
    const float* __restrict__ x, const float* __restrict__ bias,
    float* __restrict__ out)
{
    extern __shared__ char smem[];
    uint32_t sb = s2u(smem);

    const int t    = threadIdx.x;
    const int lane = t & 31;
    const int wid  = t >> 5;
    const int mw   = wid >> 1;     // 0..3 -> rows mw*64
    const int nw   = wid & 1;      // 0..1 -> cols nw*32
    const int pbase = blockIdx.x * 64;
    const int b     = pbase >> 12;
    const int pib   = pbase & 4095;

    uint32_t* s_idxA = (uint32_t*)(smem + SM_IDXA);
    float4*   s_wq   = (float4*)(smem + SM_WQ);

    // ---- sampling params: 9 kk x 64 pixels ----
    for (int e = t; e < KK_ * 64; e += 256) {
        int kk = e >> 6;
        int n  = e & 63;
        int pimg = pib + n;
        int h = pimg >> 6, w = pimg & 63;
        const float* omb = g_om + (((size_t)b * OMCH) << 12) + pimg;
        float dy = omb[(size_t)(2 * kk) << 12];
        float dx = omb[(size_t)(2 * kk + 1) << 12];
        float mv = omb[(size_t)(18 + kk) << 12];
        float m  = 1.0f / (1.0f + expf(-mv));
        int kh = kk / 3, kw = kk - 3 * kh;
        float py = (float)(h - 1 + kh) + dy;
        float px = (float)(w - 1 + kw) + dx;
        float y0f = floorf(py), x0f = floorf(px);
        float ly = py - y0f, lx = px - x0f;
        int y0 = (int)y0f, x0 = (int)x0f;
        int y1 = y0 + 1, x1 = x0 + 1;
        float vy0 = ((unsigned)y0 < 64u) ? 1.f : 0.f;
        float vy1 = ((unsigned)y1 < 64u) ? 1.f : 0.f;
        float vx0 = ((unsigned)x0 < 64u) ? 1.f : 0.f;
        float vx1 = ((unsigned)x1 < 64u) ? 1.f : 0.f;
        int y0c = min(max(y0, 0), 63), y1c = min(max(y1, 0), 63);
        int x0c = min(max(x0, 0), 63), x1c = min(max(x1, 0), 63);
        float w00 = (1.f - ly) * (1.f - lx) * m * vy0 * vx0;
        float w01 = (1.f - ly) * lx * m * vy0 * vx1;
        float w10 = ly * (1.f - lx) * m * vy1 * vx0;
        float w11 = ly * lx * m * vy1 * vx1;
        uint32_t f = (y1c != y0c) ? 1u : 0u;
        s_idxA[e] = (uint32_t)(y0c * 64 + x0c) | (f << 12)
                  | ((uint32_t)(y0c * 64 + x1c) << 16);
        s_wq[e] = make_float4(w00, w01, w10, w11);
    }

    float acc[4][4][4];
#pragma unroll
    for (int i = 0; i < 4; i++)
#pragma unroll
        for (int j = 0; j < 4; j++)
#pragma unroll
            for (int q = 0; q < 4; q++) acc[i][j][q] = 0.f;

    const uint32_t a_off = (uint32_t)((lane & 15) * 80 + ((lane >> 4) << 4));
    const uint32_t b_off = (uint32_t)((((lane >> 4) << 3) + (lane & 7)) * 80
                                      + (((lane >> 3) & 1) << 4));

    const float* xb = x + ((size_t)b << 20);
    const int nloc  = t & 63;      // pixel in 64-px tile
    const int klq   = t >> 6;      // 0..3: channel octet kl = klq*8 + j

    auto load_ctx = [&](int c, GatherCtx& g) {
        int kk = c >> 3, cg = c & 7;
        int e  = (kk << 6) + nloc;
        uint32_t ia = s_idxA[e];
        int f  = (ia >> 12) & 1;
        g.i00 = ia & 0xfff;
        g.i01 = ia >> 16;
        g.i10 = g.i00 + (f << 6);
        g.i11 = g.i01 + (f << 6);
        g.wq  = s_wq[e];
        g.xch = xb + ((size_t)(cg * 32 + klq * 8) << 12);
    };

    auto loadA = [&](uint32_t base, int h, uint32_t (*f)[4]) {
#pragma unroll
        for (int mi = 0; mi < 4; mi++)
            ldsm4(f[mi], base + a_off + (uint32_t)((mw * 64 + mi * 16) * 80 + h * 32));
    };
    auto loadB = [&](uint32_t base, int h, uint32_t (*f)[4]) {
#pragma unroll
        for (int p = 0; p < 2; p++)
            ldsm4(f[p], base + b_off + (uint32_t)((nw * 32 + p * 16) * 80 + h * 32));
    };
    auto mma_block = [&](uint32_t (*af)[4], uint32_t (*bf)[4]) {
#pragma unroll
        for (int mi = 0; mi < 4; mi++)
#pragma unroll
            for (int p = 0; p < 2; p++) {
                mma_bf16(acc[mi][2 * p],     af[mi], &bf[p][0]);
                mma_bf16(acc[mi][2 * p + 1], af[mi], &bf[p][2]);
            }
    };

    const uint32_t bstore = (uint32_t)(nloc * 80 + klq * 16);

    uint32_t ph[4], pl[4];

    // ---- prologue: A(0) cp.async; params sync; B(0) gathered into regs ----
    {
        const float4* srcA = g_wA;
        uint32_t dA = sb + SM_A;
#pragma unroll
        for (int r = 0; r < 10; r++)
            cp_async16(dA + (uint32_t)((t + (r << 8)) << 4), srcA + t + (r << 8));
        cp_commit();

        __syncthreads();   // params visible

        GatherCtx g; load_ctx(0, g);
        float v[8], r[8];
#pragma unroll
        for (int grp = 0; grp < 4; grp++) {
            gather_issue(g, grp, r);
            gather_combine(g, r, v[2 * grp], v[2 * grp + 1]);
        }
        pack4(v, ph, pl);
    }

    for (int c = 0; c < NCH; c++) {
        const int buf = c & 1;

        // ---- STS B(c) (slot freed by the sync of iteration c-1) ----
        {
            char* bh = smem + SM_B + buf * 10240 + bstore;
            *(float4*)bh          = *(float4*)ph;
            *(float4*)(bh + 5120) = *(float4*)pl;
        }
        cp_wait0();          // A(c) resident
        __syncthreads();

        const bool pf = (c + 1 < NCH);
        if (pf) {
            const float4* srcA = g_wA + (size_t)(c + 1) * 2560;
            uint32_t dA = sb + SM_A + (buf ^ 1) * 40960;
#pragma unroll
            for (int rr = 0; rr < 10; rr++)
                cp_async16(dA + (uint32_t)((t + (rr << 8)) << 4), srcA + t + (rr << 8));
            cp_commit();
        }

        GatherCtx g;
        float v[8], r[8];
        if (pf) { load_ctx(c + 1, g); gather_issue(g, 0, r); }

        const uint32_t Ah0 = sb + SM_A + buf * 40960;
        const uint32_t Al0 = Ah0 + 20480;
        const uint32_t Bh0 = sb + SM_B + buf * 10240;
        const uint32_t Bl0 = Bh0 + 5120;

        uint32_t afh[4][4], afl[4][4], bfh[2][4], bfl[2][4];

        // ---- h = 0: Ah,Bh -> AhBh; Bl -> AhBl; Al -> AlBh ----
        loadA(Ah0, 0, afh); loadB(Bh0, 0, bfh);
        mma_block(afh, bfh);
        if (pf) { gather_combine(g, r, v[0], v[1]); gather_issue(g, 1, r); }
        loadB(Bl0, 0, bfl);
        mma_block(afh, bfl);
        if (pf) { gather_combine(g, r, v[2], v[3]); gather_issue(g, 2, r); }
        loadA(Al0, 0, afl);
        mma_block(afl, bfh);
        if (pf) { gather_combine(g, r, v[4], v[5]); gather_issue(g, 3, r); }

        // ---- h = 1: same pattern ----
        loadA(Ah0, 1, afh); loadB(Bh0, 1, bfh);
        mma_block(afh, bfh);
        loadB(Bl0, 1, bfl);
        mma_block(afh, bfl);
        if (pf) gather_combine(g, r, v[6], v[7]);
        loadA(Al0, 1, afl);
        mma_block(afl, bfh);
        if (pf) pack4(v, ph, pl);   // STS happens at top of next iteration
    }

    // ---- epilogue: bias + store ----
    const int m0   = mw * 64 + (lane >> 2);
    const int col0 = nw * 32 + ((lane & 3) << 1);
#pragma unroll
    for (int mi = 0; mi < 4; mi++) {
        int o = m0 + mi * 16;
        float bv0 = __ldg(bias + o);
        float bv1 = __ldg(bias + o + 8);
        float* r0 = out + (((size_t)(b * O_ + o)) << 12) + pib;
        float* r1 = r0 + (8 << 12);
#pragma unroll
        for (int nj = 0; nj < 4; nj++) {
            int cc = col0 + nj * 8;
            float2 v0 = make_float2(acc[mi][nj][0] + bv0, acc[mi][nj][1] + bv0);
            float2 v1 = make_float2(acc[mi][nj][2] + bv1, acc[mi][nj][3] + bv1);
            *(float2*)(r0 + cc) = v0;
            *(float2*)(r1 + cc) = v1;
        }
    }
}

// ---------------------------------------------------------------------------
// Launch
// ---------------------------------------------------------------------------
extern "C" void kernel_launch(void* const* d_in, const int* in_sizes, int n_in,
                              void* d_out, int out_size)
{
    const float* x      = (const float*)d_in[0];
    const float* w_off  = (const float*)d_in[1];
    const float* b_off  = (const float*)d_in[2];
    const float* weight = (const float*)d_in[3];
    const float* bias   = (const float*)d_in[4];
    float* out = (float*)d_out;

    cudaFuncSetAttribute(dcn_mma_kernel,
                         cudaFuncAttributeMaxDynamicSharedMemorySize, DYN_SMEM);
    cudaFuncSetAttribute(om_mma_kernel,
                         cudaFuncAttributeMaxDynamicSharedMemorySize, OM_SMEM);

    prep_w_kernel<<<2304, 256>>>(weight);
    prep_woff_kernel<<<288, 256>>>(w_off);
    om_mma_kernel<<<128, 256, OM_SMEM>>>(x, b_off);
    dcn_mma_kernel<<<NPIX / 64, 256, DYN_SMEM>>>(x, bias, out);
}

// round 12
// speedup vs baseline: 1.0289x; 1.0289x over previous
#include <cuda_runtime.h>
#include <cuda_bf16.h>
#include <cstdint>

// Problem constants
#define B_    4
#define C_    256
#define H_    64
#define W_    64
#define O_    256
#define KK_   9
#define HW_   4096
#define NPIX  16384
#define KTOT  2304
#define OMCH  27
#define OMSZ  (B_*OMCH*HW_)   // 442368

// GEMM chunking: k' = kk*256 + c; 72 chunks of 32 channels
#define NCH   72
#define KPAD  40              // padded K row -> 80B rows, conflict-free ldmatrix/STS.128

// Device scratch
__device__ float  g_om[OMSZ];
__device__ float  g_xt[(size_t)B_ * HW_ * C_];     // x transposed: [b][pos][c], 16MB
// main GEMM weights: per chunk [hi 256x40 bf16][lo 256x40 bf16] = 40960 B
__device__ float4 g_wA[NCH * 2560];
// offset-conv weights: per chunk [hi 32x40 bf16][lo 32x40 bf16] = 5120 B
__device__ __nv_bfloat16 g_wOff[NCH * 2560];

// ---------------------------------------------------------------------------
// PTX helpers
// ---------------------------------------------------------------------------
__device__ __forceinline__ uint32_t s2u(const void* p) {
    uint32_t r;
    asm("{ .reg .u64 t; cvta.to.shared.u64 t, %1; cvt.u32.u64 %0, t; }" : "=r"(r) : "l"(p));
    return r;
}
__device__ __forceinline__ void ldsm4(uint32_t* r, uint32_t addr) {
    asm volatile("ldmatrix.sync.aligned.m8n8.x4.shared.b16 {%0,%1,%2,%3}, [%4];"
                 : "=r"(r[0]), "=r"(r[1]), "=r"(r[2]), "=r"(r[3]) : "r"(addr));
}
__device__ __forceinline__ void mma_bf16(float* d, const uint32_t* a, const uint32_t* b) {
    asm volatile(
        "mma.sync.aligned.m16n8k16.row.col.f32.bf16.bf16.f32 "
        "{%0,%1,%2,%3}, {%4,%5,%6,%7}, {%8,%9}, {%0,%1,%2,%3};"
        : "+f"(d[0]), "+f"(d[1]), "+f"(d[2]), "+f"(d[3])
        : "r"(a[0]), "r"(a[1]), "r"(a[2]), "r"(a[3]), "r"(b[0]), "r"(b[1]));
}
__device__ __forceinline__ void cp_async16(uint32_t dst, const void* src) {
    asm volatile("cp.async.cg.shared.global [%0], [%1], 16;" :: "r"(dst), "l"(src));
}
__device__ __forceinline__ void cp_commit() {
    asm volatile("cp.async.commit_group;" ::: "memory");
}
__device__ __forceinline__ void cp_wait0() {
    asm volatile("cp.async.wait_group 0;" ::: "memory");
}
__device__ __forceinline__ void cp_wait1() {
    asm volatile("cp.async.wait_group 1;" ::: "memory");
}
__device__ __forceinline__ void pack4(const float* v, uint32_t* ph, uint32_t* pl) {
#pragma unroll
    for (int q = 0; q < 4; q++) {
        uint32_t ua = __float_as_uint(v[2 * q]);
        uint32_t ub = __float_as_uint(v[2 * q + 1]);
        float ta = __uint_as_float(ua & 0xffff0000u);
        float tb = __uint_as_float(ub & 0xffff0000u);
        ph[q] = __byte_perm(ua, ub, 0x7632);
        pl[q] = __byte_perm(__float_as_uint(v[2 * q] - ta),
                            __float_as_uint(v[2 * q + 1] - tb), 0x7632);
    }
}

// ---------------------------------------------------------------------------
// SMEM layout (main kernel): A ring x3, B ring x3, params
// ---------------------------------------------------------------------------
#define SM_A     0        // 3 x 40960
#define SM_B     122880   // 3 x 20480
#define SM_IDXA  184320
#define SM_IDXB  188928
#define SM_WQ    193536
#define DYN_SMEM 211968

// om kernel smem: A 2x5120, B 2x20480
#define OM_A     0
#define OM_B     10240
#define OM_SMEM  51200

// ---------------------------------------------------------------------------
// Kernel 1a: pack main weights into bf16 hi/lo padded tiles
// ---------------------------------------------------------------------------
__global__ void prep_w_kernel(const float* __restrict__ weight) {
    int i = blockIdx.x * 256 + threadIdx.x;   // 0 .. 589823
    int chunk = i >> 13;
    int rem   = i & 8191;
    int o     = rem >> 5;
    int kl    = rem & 31;
    int kk = chunk >> 3;
    int cg = chunk & 7;
    int c  = cg * 32 + kl;
    float w = weight[o * KTOT + c * 9 + kk];
    __nv_bfloat16 hi = __float2bfloat16(w);
    __nv_bfloat16 lo = __float2bfloat16(w - __bfloat162float(hi));
    __nv_bfloat16* base = (__nv_bfloat16*)g_wA + (size_t)chunk * 20480;
    base[o * KPAD + kl]         = hi;
    base[10240 + o * KPAD + kl] = lo;
}

// ---------------------------------------------------------------------------
// Kernel 1b: pack offset-conv weights (27 rows, padded to 32) per chunk
// ---------------------------------------------------------------------------
__global__ void prep_woff_kernel(const float* __restrict__ w_off) {
    int i = blockIdx.x * 256 + threadIdx.x;   // 0 .. 73727
    int chunk = i >> 10;
    int rem   = i & 1023;
    int j     = rem >> 5;
    int kl    = rem & 31;
    int kk = chunk >> 3;
    int cg = chunk & 7;
    float w = (j < OMCH) ? w_off[j * KTOT + (cg * 32 + kl) * 9 + kk] : 0.f;
    __nv_bfloat16 hi = __float2bfloat16(w);
    __nv_bfloat16 lo = __float2bfloat16(w - __bfloat162float(hi));
    __nv_bfloat16* base = g_wOff + (size_t)chunk * 2560;
    base[j * KPAD + kl]        = hi;
    base[1280 + j * KPAD + kl] = lo;
}

// ---------------------------------------------------------------------------
// Kernel 1c: transpose x (NCHW -> [b][pos][c]) for coalesced gathers
// grid (128, 8, 4) x 256 thr; 32x32 smem tiles
// ---------------------------------------------------------------------------
__global__ void prep_xt_kernel(const float* __restrict__ x) {
    __shared__ float tile[32][33];
    int p0 = blockIdx.x * 32;
    int c0 = blockIdx.y * 32;
    int b  = blockIdx.z;
    int tx = threadIdx.x & 31;
    int ty = threadIdx.x >> 5;     // 0..7
    const float* xb = x + (((size_t)(b * C_ + c0)) << 12);
#pragma unroll
    for (int i = ty; i < 32; i += 8)
        tile[i][tx] = xb[((size_t)i << 12) + p0 + tx];
    __syncthreads();
    float* xtb = g_xt + ((size_t)b << 20) + ((size_t)p0 << 8) + c0;
#pragma unroll
    for (int i = ty; i < 32; i += 8)
        xtb[((size_t)i << 8) + tx] = tile[tx][i];
}

// ---------------------------------------------------------------------------
// Kernel 2: offset conv as tensor GEMM (unchanged R9).
// ---------------------------------------------------------------------------
__global__ __launch_bounds__(256, 1) void om_mma_kernel(
    const float* __restrict__ x, const float* __restrict__ bo)
{
    extern __shared__ char smem[];
    uint32_t sb = s2u(smem);

    const int t    = threadIdx.x;
    const int lane = t & 31;
    const int nw   = t >> 5;
    const int pbase = blockIdx.x * 128;
    const int b     = pbase >> 12;
    const int pib   = pbase & 4095;
    const int nloc  = t & 127;
    const int klq   = t >> 7;
    const int ph_   = (pib + nloc) >> 6;
    const int pw_   = (pib + nloc) & 63;

    const float* xb = x + ((size_t)b << 20);

    float acc[2][2][4];
#pragma unroll
    for (int i = 0; i < 2; i++)
#pragma unroll
        for (int j = 0; j < 2; j++)
#pragma unroll
            for (int q = 0; q < 4; q++) acc[i][j][q] = 0.f;

    const uint32_t a_off = (uint32_t)((lane & 15) * 80 + ((lane >> 4) << 4));
    const uint32_t b_off = (uint32_t)((((lane >> 4) << 3) + (lane & 7)) * 80
                                      + (((lane >> 3) & 1) << 4));
    const uint32_t bstore = (uint32_t)(nloc * 80 + klq * 32);

    auto buildB = [&](int c, float* v) {
        int kk = c >> 3, cg = c & 7;
        int kh = kk / 3, kw = kk - 3 * kh;
        int y  = ph_ + kh - 1;
        int xx = pw_ + kw - 1;
        bool ok = ((unsigned)y < 64u) && ((unsigned)xx < 64u);
        const float* xc = xb + ((size_t)(cg * 32 + klq * 16) << 12) + (y << 6) + xx;
#pragma unroll
        for (int j = 0; j < 16; j++)
            v[j] = ok ? __ldg(xc + ((size_t)j << 12)) : 0.f;
    };

    uint32_t ph[8], pl[8];

    {
        for (int r = 0; r < 2; r++) {
            int idx = t + (r << 8);
            if (idx < 320)
                cp_async16(sb + OM_A + (uint32_t)(idx << 4), (const char*)g_wOff + (idx << 4));
        }
        cp_commit();
        float v[16];
        buildB(0, v);
        pack4(v, ph, pl);
        pack4(v + 8, ph + 4, pl + 4);
    }

    for (int c = 0; c < NCH; c++) {
        const int buf = c & 1;

        {
            char* bh = smem + OM_B + buf * 20480 + bstore;
            *(float4*)bh                = *(float4*)(ph + 0);
            *(float4*)(bh + 16)         = *(float4*)(ph + 4);
            *(float4*)(bh + 10240)      = *(float4*)(pl + 0);
            *(float4*)(bh + 10240 + 16) = *(float4*)(pl + 4);
        }
        cp_wait0();
        __syncthreads();

        const bool pf = (c + 1 < NCH);
        if (pf) {
            const char* srcA = (const char*)(g_wOff + (size_t)(c + 1) * 2560);
            uint32_t dA = sb + OM_A + (buf ^ 1) * 5120;
            for (int r = 0; r < 2; r++) {
                int idx = t + (r << 8);
                if (idx < 320)
                    cp_async16(dA + (uint32_t)(idx << 4), srcA + (idx << 4));
            }
            cp_commit();
        }

        float v[16];
        if (pf) buildB(c + 1, v);

        const uint32_t A0 = sb + OM_A + buf * 5120;
        const uint32_t B0 = sb + OM_B + buf * 20480;
#pragma unroll
        for (int pass = 0; pass < 3; pass++) {
            uint32_t Ab = A0 + (pass == 2 ? 2560u : 0u);
            uint32_t Bb = B0 + (pass == 1 ? 10240u : 0u);
#pragma unroll
            for (int h = 0; h < 2; h++) {
                uint32_t af[2][4], bfr[4];
#pragma unroll
                for (int mi = 0; mi < 2; mi++)
                    ldsm4(af[mi], Ab + a_off + (uint32_t)((mi * 16) * 80 + h * 32));
                ldsm4(bfr, Bb + b_off + (uint32_t)((nw * 16) * 80 + h * 32));
#pragma unroll
                for (int mi = 0; mi < 2; mi++) {
                    mma_bf16(acc[mi][0], af[mi], &bfr[0]);
                    mma_bf16(acc[mi][1], af[mi], &bfr[2]);
                }
            }
        }
        if (pf) {
            pack4(v, ph, pl);
            pack4(v + 8, ph + 4, pl + 4);
        }
    }

#pragma unroll
    for (int mi = 0; mi < 2; mi++) {
#pragma unroll
        for (int half = 0; half < 2; half++) {
            int j = mi * 16 + (lane >> 2) + half * 8;
            if (j < OMCH) {
                float bv = __ldg(bo + j);
                float* row = g_om + (((size_t)(b * OMCH + j)) << 12) + pib;
#pragma unroll
                for (int nj = 0; nj < 2; nj++) {
                    int cc = nw * 16 + nj * 8 + ((lane & 3) << 1);
                    row[cc]     = acc[mi][nj][2 * half]     + bv;
                    row[cc + 1] = acc[mi][nj][2 * half + 1] + bv;
                }
            }
        }
    }
}

// ---------------------------------------------------------------------------
// Kernel 3: fused bilinear-sample + bf16 3-pass mma.sync GEMM (R10 structure).
// Gathers now hit the HWC-transposed image: thread (oct=t&3, px=t>>2) loads
// 4 neighbors x 8 contiguous channels as 8x LDG.128 (full-line wavefronts).
// ---------------------------------------------------------------------------
struct GatherCtx {
    const float4* p[4];   // per-neighbor channel-slab pointers
    float4 wq;
};

__device__ __forceinline__ void gather_issue(const GatherCtx& g, int n, float* r) {
    float4 a = __ldg(g.p[n]);
    float4 b = __ldg(g.p[n] + 1);
    r[0] = a.x; r[1] = a.y; r[2] = a.z; r[3] = a.w;
    r[4] = b.x; r[5] = b.y; r[6] = b.z; r[7] = b.w;
}
__device__ __forceinline__ void gather_acc0(const GatherCtx& g, const float* r, float* v) {
#pragma unroll
    for (int j = 0; j < 8; j++) v[j] = g.wq.x * r[j];
}
__device__ __forceinline__ void gather_acc(float w, const float* r, float* v) {
#pragma unroll
    for (int j = 0; j < 8; j++) v[j] += w * r[j];
}

__global__ __launch_bounds__(512, 1) void dcn_mma_kernel(
    const float* __restrict__ x, const float* __restrict__ bias,
    float* __restrict__ out)
{
    extern __shared__ char smem[];
    uint32_t sb = s2u(smem);

    const int t    = threadIdx.x;
    const int lane = t & 31;
    const int wid  = t >> 5;
    const int mw   = wid >> 2;
    const int nw   = wid & 3;
    const int pbase = blockIdx.x * 128;
    const int b     = pbase >> 12;
    const int pib   = pbase & 4095;

    uint32_t* s_idxA = (uint32_t*)(smem + SM_IDXA);
    uint32_t* s_idxB = (uint32_t*)(smem + SM_IDXB);
    float4*   s_wq   = (float4*)(smem + SM_WQ);

    // ---- sampling params: 9 kk x 128 pixels ----
    for (int e = t; e < KK_ * 128; e += 512) {
        int kk = e >> 7;
        int n  = e & 127;
        int pimg = pib + n;
        int h = pimg >> 6, w = pimg & 63;
        const float* omb = g_om + (((size_t)b * OMCH) << 12) + pimg;
        float dy = omb[(size_t)(2 * kk) << 12];
        float dx = omb[(size_t)(2 * kk + 1) << 12];
        float mv = omb[(size_t)(18 + kk) << 12];
        float m  = 1.0f / (1.0f + expf(-mv));
        int kh = kk / 3, kw = kk - 3 * kh;
        float py = (float)(h - 1 + kh) + dy;
        float px = (float)(w - 1 + kw) + dx;
        float y0f = floorf(py), x0f = floorf(px);
        float ly = py - y0f, lx = px - x0f;
        int y0 = (int)y0f, x0 = (int)x0f;
        int y1 = y0 + 1, x1 = x0 + 1;
        float vy0 = ((unsigned)y0 < 64u) ? 1.f : 0.f;
        float vy1 = ((unsigned)y1 < 64u) ? 1.f : 0.f;
        float vx0 = ((unsigned)x0 < 64u) ? 1.f : 0.f;
        float vx1 = ((unsigned)x1 < 64u) ? 1.f : 0.f;
        int y0c = min(max(y0, 0), 63), y1c = min(max(y1, 0), 63);
        int x0c = min(max(x0, 0), 63), x1c = min(max(x1, 0), 63);
        float w00 = (1.f - ly) * (1.f - lx) * m * vy0 * vx0;
        float w01 = (1.f - ly) * lx * m * vy0 * vx1;
        float w10 = ly * (1.f - lx) * m * vy1 * vx0;
        float w11 = ly * lx * m * vy1 * vx1;
        s_idxA[e] = (uint32_t)(y0c * 64 + x0c) | ((uint32_t)(y0c * 64 + x1c) << 16);
        s_idxB[e] = (uint32_t)(y1c * 64 + x0c) | ((uint32_t)(y1c * 64 + x1c) << 16);
        s_wq[e] = make_float4(w00, w01, w10, w11);
    }

    float acc[4][4][4];
#pragma unroll
    for (int i = 0; i < 4; i++)
#pragma unroll
        for (int j = 0; j < 4; j++)
#pragma unroll
            for (int q = 0; q < 4; q++) acc[i][j][q] = 0.f;

    const uint32_t a_off = (uint32_t)((lane & 15) * 80 + ((lane >> 4) << 4));
    const uint32_t b_off = (uint32_t)((((lane >> 4) << 3) + (lane & 7)) * 80
                                      + (((lane >> 3) & 1) << 4));

    const float* xtb = g_xt + ((size_t)b << 20);
    const int oct  = t & 3;       // channel octet within chunk
    const int pxl  = t >> 2;      // pixel in 128-px tile

    auto load_ctx = [&](int c, GatherCtx& g) {
        int kk = c >> 3, cg = c & 7;
        int e  = (kk << 7) + pxl;
        uint32_t ia = s_idxA[e], ib2 = s_idxB[e];
        int choff = cg * 32 + oct * 8;
        g.p[0] = (const float4*)(xtb + ((size_t)(ia & 0xffffu) << 8) + choff);
        g.p[1] = (const float4*)(xtb + ((size_t)(ia >> 16) << 8) + choff);
        g.p[2] = (const float4*)(xtb + ((size_t)(ib2 & 0xffffu) << 8) + choff);
        g.p[3] = (const float4*)(xtb + ((size_t)(ib2 >> 16) << 8) + choff);
        g.wq  = s_wq[e];
    };

    auto loadA = [&](uint32_t base, int h, uint32_t (*f)[4]) {
#pragma unroll
        for (int mi = 0; mi < 4; mi++)
            ldsm4(f[mi], base + a_off + (uint32_t)((mw * 64 + mi * 16) * 80 + h * 32));
    };
    auto loadB = [&](uint32_t base, int h, uint32_t (*f)[4]) {
#pragma unroll
        for (int p = 0; p < 2; p++)
            ldsm4(f[p], base + b_off + (uint32_t)((nw * 32 + p * 16) * 80 + h * 32));
    };
    auto mma_block = [&](uint32_t (*af)[4], uint32_t (*bf)[4]) {
#pragma unroll
        for (int mi = 0; mi < 4; mi++)
#pragma unroll
            for (int p = 0; p < 2; p++) {
                mma_bf16(acc[mi][2 * p],     af[mi], &bf[p][0]);
                mma_bf16(acc[mi][2 * p + 1], af[mi], &bf[p][2]);
            }
    };

    const uint32_t bstore = (uint32_t)(pxl * 80 + oct * 16);

    // ---- prologue ----
    {
        const float4* srcA0 = g_wA;
        uint32_t dA0 = sb + SM_A;
#pragma unroll
        for (int r = 0; r < 5; r++)
            cp_async16(dA0 + (uint32_t)((t + (r << 9)) << 4), srcA0 + t + (r << 9));
        cp_commit();
        const float4* srcA1 = g_wA + 2560;
        uint32_t dA1 = sb + SM_A + 40960;
#pragma unroll
        for (int r = 0; r < 5; r++)
            cp_async16(dA1 + (uint32_t)((t + (r << 9)) << 4), srcA1 + t + (r << 9));
        cp_commit();

        __syncthreads();

        GatherCtx g; load_ctx(0, g);
        float v[8], r[8];
        gather_issue(g, 0, r); gather_acc0(g, r, v);
        gather_issue(g, 1, r); gather_acc(g.wq.y, r, v);
        gather_issue(g, 2, r); gather_acc(g.wq.z, r, v);
        gather_issue(g, 3, r); gather_acc(g.wq.w, r, v);
        uint32_t ph[4], pl[4];
        pack4(v, ph, pl);
        char* bh = smem + SM_B + bstore;
        *(float4*)bh           = *(float4*)ph;
        *(float4*)(bh + 10240) = *(float4*)pl;

        cp_wait1();
        __syncthreads();
    }

    int cb = 0;
    for (int c = 0; c < NCH; c++) {
        const int nb = (cb == 2) ? 0 : cb + 1;
        const int pb = (nb == 2) ? 0 : nb + 1;

        const uint32_t Ah0 = sb + SM_A + cb * 40960;
        const uint32_t Al0 = Ah0 + 20480;
        const uint32_t Bh0 = sb + SM_B + cb * 20480;
        const uint32_t Bl0 = Bh0 + 10240;

        const bool pf = (c + 1 < NCH);
        GatherCtx g;
        float v[8], r[8];
        if (pf) { load_ctx(c + 1, g); gather_issue(g, 0, r); }

        uint32_t afh[4][4], afl[4][4], bfh[2][4], bfl[2][4];

        // ---- h = 0: Ah,Bh -> AhBh; Bl -> AhBl; Al -> AlBh ----
        loadA(Ah0, 0, afh); loadB(Bh0, 0, bfh);
        mma_block(afh, bfh);
        if (pf) { gather_acc0(g, r, v); gather_issue(g, 1, r); }
        loadB(Bl0, 0, bfl);
        mma_block(afh, bfl);
        if (pf) { gather_acc(g.wq.y, r, v); gather_issue(g, 2, r); }
        loadA(Al0, 0, afl);
        mma_block(afl, bfh);
        if (pf) { gather_acc(g.wq.z, r, v); gather_issue(g, 3, r); }

        // ---- h = 1: same pattern ----
        loadA(Ah0, 1, afh); loadB(Bh0, 1, bfh);
        mma_block(afh, bfh);
        if (pf) {
            gather_acc(g.wq.w, r, v);
            uint32_t ph[4], pl[4];
            pack4(v, ph, pl);
            char* bh = smem + SM_B + nb * 20480 + bstore;
            *(float4*)bh           = *(float4*)ph;
            *(float4*)(bh + 10240) = *(float4*)pl;
        }
        if (c + 2 < NCH) {
            const float4* srcA = g_wA + (size_t)(c + 2) * 2560;
            uint32_t dA = sb + SM_A + pb * 40960;
#pragma unroll
            for (int rr = 0; rr < 5; rr++)
                cp_async16(dA + (uint32_t)((t + (rr << 9)) << 4), srcA + t + (rr << 9));
            cp_commit();
        }
        loadB(Bl0, 1, bfl);
        mma_block(afh, bfl);
        loadA(Al0, 1, afl);
        mma_block(afl, bfh);

        if (c + 2 < NCH) cp_wait1();
        else             cp_wait0();
        __syncthreads();
        cb = nb;
    }

    // ---- epilogue ----
    const int m0   = mw * 64 + (lane >> 2);
    const int col0 = nw * 32 + ((lane & 3) << 1);
#pragma unroll
    for (int mi = 0; mi < 4; mi++) {
        int o = m0 + mi * 16;
        float bv0 = __ldg(bias + o);
        float bv1 = __ldg(bias + o + 8);
        float* r0 = out + (((size_t)(b * O_ + o)) << 12) + pib;
        float* r1 = r0 + (8 << 12);
#pragma unroll
        for (int nj = 0; nj < 4; nj++) {
            int cc = col0 + nj * 8;
            float2 v0 = make_float2(acc[mi][nj][0] + bv0, acc[mi][nj][1] + bv0);
            float2 v1 = make_float2(acc[mi][nj][2] + bv1, acc[mi][nj][3] + bv1);
            *(float2*)(r0 + cc) = v0;
            *(float2*)(r1 + cc) = v1;
        }
    }
}

// ---------------------------------------------------------------------------
// Launch
// ---------------------------------------------------------------------------
extern "C" void kernel_launch(void* const* d_in, const int* in_sizes, int n_in,
                              void* d_out, int out_size)
{
    const float* x      = (const float*)d_in[0];
    const float* w_off  = (const float*)d_in[1];
    const float* b_off  = (const float*)d_in[2];
    const float* weight = (const float*)d_in[3];
    const float* bias   = (const float*)d_in[4];
    float* out = (float*)d_out;

    cudaFuncSetAttribute(dcn_mma_kernel,
                         cudaFuncAttributeMaxDynamicSharedMemorySize, DYN_SMEM);
    cudaFuncSetAttribute(om_mma_kernel,
                         cudaFuncAttributeMaxDynamicSharedMemorySize, OM_SMEM);

    prep_w_kernel<<<2304, 256>>>(weight);
    prep_woff_kernel<<<288, 256>>>(w_off);
    prep_xt_kernel<<<dim3(128, 8, 4), 256>>>(x);
    om_mma_kernel<<<128, 256, OM_SMEM>>>(x, b_off);
    dcn_mma_kernel<<<NPIX / 128, 512, DYN_SMEM>>>(x, bias, out);
}

// round 13
// speedup vs baseline: 1.0364x; 1.0073x over previous
#include <cuda_runtime.h>
#include <cuda_bf16.h>
#include <cstdint>

// Problem constants
#define B_    4
#define C_    256
#define H_    64
#define W_    64
#define O_    256
#define KK_   9
#define HW_   4096
#define NPIX  16384
#define KTOT  2304
#define OMCH  27
#define OMSZ  (B_*OMCH*HW_)   // 442368

// GEMM chunking: k' = kk*256 + c; 72 chunks of 32 channels
#define NCH   72
#define KPAD  40              // padded K row -> 80B rows, conflict-free ldmatrix/STS.128

// Device scratch
__device__ float  g_om[OMSZ];
__device__ float  g_xt[(size_t)B_ * HW_ * C_];     // x transposed: [b][pos][c], 16MB
// main GEMM weights: per chunk [hi 256x40 bf16][lo 256x40 bf16] = 40960 B
__device__ float4 g_wA[NCH * 2560];
// offset-conv weights: per chunk [hi 32x40 bf16][lo 32x40 bf16] = 5120 B
__device__ __nv_bfloat16 g_wOff[NCH * 2560];

// ---------------------------------------------------------------------------
// PTX helpers
// ---------------------------------------------------------------------------
__device__ __forceinline__ uint32_t s2u(const void* p) {
    uint32_t r;
    asm("{ .reg .u64 t; cvta.to.shared.u64 t, %1; cvt.u32.u64 %0, t; }" : "=r"(r) : "l"(p));
    return r;
}
__device__ __forceinline__ void ldsm4(uint32_t* r, uint32_t addr) {
    asm volatile("ldmatrix.sync.aligned.m8n8.x4.shared.b16 {%0,%1,%2,%3}, [%4];"
                 : "=r"(r[0]), "=r"(r[1]), "=r"(r[2]), "=r"(r[3]) : "r"(addr));
}
__device__ __forceinline__ void mma_bf16(float* d, const uint32_t* a, const uint32_t* b) {
    asm volatile(
        "mma.sync.aligned.m16n8k16.row.col.f32.bf16.bf16.f32 "
        "{%0,%1,%2,%3}, {%4,%5,%6,%7}, {%8,%9}, {%0,%1,%2,%3};"
        : "+f"(d[0]), "+f"(d[1]), "+f"(d[2]), "+f"(d[3])
        : "r"(a[0]), "r"(a[1]), "r"(a[2]), "r"(a[3]), "r"(b[0]), "r"(b[1]));
}
__device__ __forceinline__ void cp_async16(uint32_t dst, const void* src) {
    asm volatile("cp.async.cg.shared.global [%0], [%1], 16;" :: "r"(dst), "l"(src));
}
__device__ __forceinline__ void cp_commit() {
    asm volatile("cp.async.commit_group;" ::: "memory");
}
__device__ __forceinline__ void cp_wait0() {
    asm volatile("cp.async.wait_group 0;" ::: "memory");
}
__device__ __forceinline__ void cp_wait1() {
    asm volatile("cp.async.wait_group 1;" ::: "memory");
}
__device__ __forceinline__ void pack4(const float* v, uint32_t* ph, uint32_t* pl) {
#pragma unroll
    for (int q = 0; q < 4; q++) {
        uint32_t ua = __float_as_uint(v[2 * q]);
        uint32_t ub = __float_as_uint(v[2 * q + 1]);
        float ta = __uint_as_float(ua & 0xffff0000u);
        float tb = __uint_as_float(ub & 0xffff0000u);
        ph[q] = __byte_perm(ua, ub, 0x7632);
        pl[q] = __byte_perm(__float_as_uint(v[2 * q] - ta),
                            __float_as_uint(v[2 * q + 1] - tb), 0x7632);
    }
}

// ---------------------------------------------------------------------------
// SMEM layout (main kernel): A ring x3, B ring x3, params
// ---------------------------------------------------------------------------
#define SM_A     0        // 3 x 40960
#define SM_B     122880   // 3 x 20480
#define SM_IDXA  184320
#define SM_IDXB  188928
#define SM_WQ    193536
#define DYN_SMEM 211968

// om kernel smem: A ring 2 x 10240 (2 chunks), B ring 2 x 40960 (2 chunks)
#define OM_A     0
#define OM_B     20480
#define OM_SMEM  102400

// ---------------------------------------------------------------------------
// Kernel 1a: pack main weights into bf16 hi/lo padded tiles
// ---------------------------------------------------------------------------
__global__ void prep_w_kernel(const float* __restrict__ weight) {
    int i = blockIdx.x * 256 + threadIdx.x;   // 0 .. 589823
    int chunk = i >> 13;
    int rem   = i & 8191;
    int o     = rem >> 5;
    int kl    = rem & 31;
    int kk = chunk >> 3;
    int cg = chunk & 7;
    int c  = cg * 32 + kl;
    float w = weight[o * KTOT + c * 9 + kk];
    __nv_bfloat16 hi = __float2bfloat16(w);
    __nv_bfloat16 lo = __float2bfloat16(w - __bfloat162float(hi));
    __nv_bfloat16* base = (__nv_bfloat16*)g_wA + (size_t)chunk * 20480;
    base[o * KPAD + kl]         = hi;
    base[10240 + o * KPAD + kl] = lo;
}

// ---------------------------------------------------------------------------
// Kernel 1b: pack offset-conv weights (27 rows, padded to 32) per chunk
// ---------------------------------------------------------------------------
__global__ void prep_woff_kernel(const float* __restrict__ w_off) {
    int i = blockIdx.x * 256 + threadIdx.x;   // 0 .. 73727
    int chunk = i >> 10;
    int rem   = i & 1023;
    int j     = rem >> 5;
    int kl    = rem & 31;
    int kk = chunk >> 3;
    int cg = chunk & 7;
    float w = (j < OMCH) ? w_off[j * KTOT + (cg * 32 + kl) * 9 + kk] : 0.f;
    __nv_bfloat16 hi = __float2bfloat16(w);
    __nv_bfloat16 lo = __float2bfloat16(w - __bfloat162float(hi));
    __nv_bfloat16* base = g_wOff + (size_t)chunk * 2560;
    base[j * KPAD + kl]        = hi;
    base[1280 + j * KPAD + kl] = lo;
}

// ---------------------------------------------------------------------------
// Kernel 1c: transpose x (NCHW -> [b][pos][c]) for coalesced gathers
// ---------------------------------------------------------------------------
__global__ void prep_xt_kernel(const float* __restrict__ x) {
    __shared__ float tile[32][33];
    int p0 = blockIdx.x * 32;
    int c0 = blockIdx.y * 32;
    int b  = blockIdx.z;
    int tx = threadIdx.x & 31;
    int ty = threadIdx.x >> 5;     // 0..7
    const float* xb = x + (((size_t)(b * C_ + c0)) << 12);
#pragma unroll
    for (int i = ty; i < 32; i += 8)
        tile[i][tx] = xb[((size_t)i << 12) + p0 + tx];
    __syncthreads();
    float* xtb = g_xt + ((size_t)b << 20) + ((size_t)p0 << 8) + c0;
#pragma unroll
    for (int i = ty; i < 32; i += 8)
        xtb[((size_t)i << 8) + tx] = tile[tx][i];
}

// ---------------------------------------------------------------------------
// Kernel 2: offset conv as tensor GEMM. M=32 (27 used) x N=128 px per CTA.
// 2 K-chunks per sync period (36 periods) to cut barrier serialization.
// ---------------------------------------------------------------------------
__global__ __launch_bounds__(256, 1) void om_mma_kernel(
    const float* __restrict__ x, const float* __restrict__ bo)
{
    extern __shared__ char smem[];
    uint32_t sb = s2u(smem);

    const int t    = threadIdx.x;
    const int lane = t & 31;
    const int nw   = t >> 5;
    const int pbase = blockIdx.x * 128;
    const int b     = pbase >> 12;
    const int pib   = pbase & 4095;
    const int nloc  = t & 127;
    const int klq   = t >> 7;
    const int ph_   = (pib + nloc) >> 6;
    const int pw_   = (pib + nloc) & 63;

    const float* xb = x + ((size_t)b << 20);

    float acc[2][2][4];
#pragma unroll
    for (int i = 0; i < 2; i++)
#pragma unroll
        for (int j = 0; j < 2; j++)
#pragma unroll
            for (int q = 0; q < 4; q++) acc[i][j][q] = 0.f;

    const uint32_t a_off = (uint32_t)((lane & 15) * 80 + ((lane >> 4) << 4));
    const uint32_t b_off = (uint32_t)((((lane >> 4) << 3) + (lane & 7)) * 80
                                      + (((lane >> 3) & 1) << 4));
    const uint32_t bstore = (uint32_t)(nloc * 80 + klq * 32);

    auto buildB = [&](int c, float* v) {
        int kk = c >> 3, cg = c & 7;
        int kh = kk / 3, kw = kk - 3 * kh;
        int y  = ph_ + kh - 1;
        int xx = pw_ + kw - 1;
        bool ok = ((unsigned)y < 64u) && ((unsigned)xx < 64u);
        const float* xc = xb + ((size_t)(cg * 32 + klq * 16) << 12) + (y << 6) + xx;
#pragma unroll
        for (int j = 0; j < 16; j++)
            v[j] = ok ? __ldg(xc + ((size_t)j << 12)) : 0.f;
    };

    uint32_t phA[8], plA[8], phB[8], plB[8];

    // ---- prologue: A(chunks 0,1) cp.async; B(0),B(1) built ----
    {
        for (int r = 0; r < 3; r++) {
            int idx = t + (r << 8);
            if (idx < 640)
                cp_async16(sb + OM_A + (uint32_t)(idx << 4), (const char*)g_wOff + (idx << 4));
        }
        cp_commit();
        float v[16];
        buildB(0, v);
        pack4(v, phA, plA); pack4(v + 8, phA + 4, plA + 4);
        buildB(1, v);
        pack4(v, phB, plB); pack4(v + 8, phB + 4, plB + 4);
    }

    for (int cp = 0; cp < NCH / 2; cp++) {
        const int buf = cp & 1;

        // ---- STS both chunks of this period ----
        {
            char* b0 = smem + OM_B + buf * 40960 + bstore;
            char* b1 = b0 + 20480;
            *(float4*)b0                = *(float4*)(phA + 0);
            *(float4*)(b0 + 16)         = *(float4*)(phA + 4);
            *(float4*)(b0 + 10240)      = *(float4*)(plA + 0);
            *(float4*)(b0 + 10240 + 16) = *(float4*)(plA + 4);
            *(float4*)b1                = *(float4*)(phB + 0);
            *(float4*)(b1 + 16)         = *(float4*)(phB + 4);
            *(float4*)(b1 + 10240)      = *(float4*)(plB + 0);
            *(float4*)(b1 + 10240 + 16) = *(float4*)(plB + 4);
        }
        cp_wait0();
        __syncthreads();

        const bool pf = (cp + 1 < NCH / 2);
        if (pf) {
            const char* srcA = (const char*)(g_wOff + (size_t)(2 * cp + 2) * 2560);
            uint32_t dA = sb + OM_A + (buf ^ 1) * 10240;
            for (int r = 0; r < 3; r++) {
                int idx = t + (r << 8);
                if (idx < 640)
                    cp_async16(dA + (uint32_t)(idx << 4), srcA + (idx << 4));
            }
            cp_commit();
        }

        float v0[16], v1[16];
        if (pf) { buildB(2 * cp + 2, v0); buildB(2 * cp + 3, v1); }  // 32 LDGs in flight

#pragma unroll
        for (int sub = 0; sub < 2; sub++) {
            const uint32_t A0 = sb + OM_A + buf * 10240 + sub * 5120;
            const uint32_t B0 = sb + OM_B + buf * 40960 + sub * 20480;
#pragma unroll
            for (int pass = 0; pass < 3; pass++) {
                uint32_t Ab = A0 + (pass == 2 ? 2560u : 0u);
                uint32_t Bb = B0 + (pass == 1 ? 10240u : 0u);
#pragma unroll
                for (int h = 0; h < 2; h++) {
                    uint32_t af[2][4], bfr[4];
#pragma unroll
                    for (int mi = 0; mi < 2; mi++)
                        ldsm4(af[mi], Ab + a_off + (uint32_t)((mi * 16) * 80 + h * 32));
                    ldsm4(bfr, Bb + b_off + (uint32_t)((nw * 16) * 80 + h * 32));
#pragma unroll
                    for (int mi = 0; mi < 2; mi++) {
                        mma_bf16(acc[mi][0], af[mi], &bfr[0]);
                        mma_bf16(acc[mi][1], af[mi], &bfr[2]);
                    }
                }
            }
        }
        if (pf) {
            pack4(v0, phA, plA); pack4(v0 + 8, phA + 4, plA + 4);
            pack4(v1, phB, plB); pack4(v1 + 8, phB + 4, plB + 4);
        }
    }

    // ---- epilogue: rows j<27 -> g_om (+bias) ----
#pragma unroll
    for (int mi = 0; mi < 2; mi++) {
#pragma unroll
        for (int half = 0; half < 2; half++) {
            int j = mi * 16 + (lane >> 2) + half * 8;
            if (j < OMCH) {
                float bv = __ldg(bo + j);
                float* row = g_om + (((size_t)(b * OMCH + j)) << 12) + pib;
#pragma unroll
                for (int nj = 0; nj < 2; nj++) {
                    int cc = nw * 16 + nj * 8 + ((lane & 3) << 1);
                    row[cc]     = acc[mi][nj][2 * half]     + bv;
                    row[cc + 1] = acc[mi][nj][2 * half + 1] + bv;
                }
            }
        }
    }
}

// ---------------------------------------------------------------------------
// Kernel 3: fused bilinear-sample + bf16 3-pass mma.sync GEMM (R12 version).
// Gathers hit the HWC-transposed image: thread (oct=t&3, px=t>>2) loads
// 4 neighbors x 8 contiguous channels as 8x LDG.128 (full-line wavefronts).
// ---------------------------------------------------------------------------
struct GatherCtx {
    const float4* p[4];   // per-neighbor channel-slab pointers
    float4 wq;
};

__device__ __forceinline__ void gather_issue(const GatherCtx& g, int n, float* r) {
    float4 a = __ldg(g.p[n]);
    float4 b = __ldg(g.p[n] + 1);
    r[0] = a.x; r[1] = a.y; r[2] = a.z; r[3] = a.w;
    r[4] = b.x; r[5] = b.y; r[6] = b.z; r[7] = b.w;
}
__device__ __forceinline__ void gather_acc0(const GatherCtx& g, const float* r, float* v) {
#pragma unroll
    for (int j = 0; j < 8; j++) v[j] = g.wq.x * r[j];
}
__device__ __forceinline__ void gather_acc(float w, const float* r, float* v) {
#pragma unroll
    for (int j = 0; j < 8; j++) v[j] += w * r[j];
}

__global__ __launch_bounds__(512, 1) void dcn_mma_kernel(
    const float* __restrict__ x, const float* __restrict__ bias,
    float* __restrict__ out)
{
    extern __shared__ char smem[];
    uint32_t sb = s2u(smem);

    const int t    = threadIdx.x;
    const int lane = t & 31;
    const int wid  = t >> 5;
    const int mw   = wid >> 2;
    const int nw   = wid & 3;
    const int pbase = blockIdx.x * 128;
    const int b     = pbase >> 12;
    const int pib   = pbase & 4095;

    uint32_t* s_idxA = (uint32_t*)(smem + SM_IDXA);
    uint32_t* s_idxB = (uint32_t*)(smem + SM_IDXB);
    float4*   s_wq   = (float4*)(smem + SM_WQ);

    // ---- sampling params: 9 kk x 128 pixels ----
    for (int e = t; e < KK_ * 128; e += 512) {
        int kk = e >> 7;
        int n  = e & 127;
        int pimg = pib + n;
        int h = pimg >> 6, w = pimg & 63;
        const float* omb = g_om + (((size_t)b * OMCH) << 12) + pimg;
        float dy = omb[(size_t)(2 * kk) << 12];
        float dx = omb[(size_t)(2 * kk + 1) << 12];
        float mv = omb[(size_t)(18 + kk) << 12];
        float m  = 1.0f / (1.0f + expf(-mv));
        int kh = kk / 3, kw = kk - 3 * kh;
        float py = (float)(h - 1 + kh) + dy;
        float px = (float)(w - 1 + kw) + dx;
        float y0f = floorf(py), x0f = floorf(px);
        float ly = py - y0f, lx = px - x0f;
        int y0 = (int)y0f, x0 = (int)x0f;
        int y1 = y0 + 1, x1 = x0 + 1;
        float vy0 = ((unsigned)y0 < 64u) ? 1.f : 0.f;
        float vy1 = ((unsigned)y1 < 64u) ? 1.f : 0.f;
        float vx0 = ((unsigned)x0 < 64u) ? 1.f : 0.f;
        float vx1 = ((unsigned)x1 < 64u) ? 1.f : 0.f;
        int y0c = min(max(y0, 0), 63), y1c = min(max(y1, 0), 63);
        int x0c = min(max(x0, 0), 63), x1c = min(max(x1, 0), 63);
        float w00 = (1.f - ly) * (1.f - lx) * m * vy0 * vx0;
        float w01 = (1.f - ly) * lx * m * vy0 * vx1;
        float w10 = ly * (1.f - lx) * m * vy1 * vx0;
        float w11 = ly * lx * m * vy1 * vx1;
        s_idxA[e] = (uint32_t)(y0c * 64 + x0c) | ((uint32_t)(y0c * 64 + x1c) << 16);
        s_idxB[e] = (uint32_t)(y1c * 64 + x0c) | ((uint32_t)(y1c * 64 + x1c) << 16);
        s_wq[e] = make_float4(w00, w01, w10, w11);
    }

    float acc[4][4][4];
#pragma unroll
    for (int i = 0; i < 4; i++)
#pragma unroll
        for (int j = 0; j < 4; j++)
#pragma unroll
            for (int q = 0; q < 4; q++) acc[i][j][q] = 0.f;

    const uint32_t a_off = (uint32_t)((lane & 15) * 80 + ((lane >> 4) << 4));
    const uint32_t b_off = (uint32_t)((((lane >> 4) << 3) + (lane & 7)) * 80
                                      + (((lane >> 3) & 1) << 4));

    const float* xtb = g_xt + ((size_t)b << 20);
    const int oct  = t & 3;       // channel octet within chunk
    const int pxl  = t >> 2;      // pixel in 128-px tile

    auto load_ctx = [&](int c, GatherCtx& g) {
        int kk = c >> 3, cg = c & 7;
        int e  = (kk << 7) + pxl;
        uint32_t ia = s_idxA[e], ib2 = s_idxB[e];
        int choff = cg * 32 + oct * 8;
        g.p[0] = (const float4*)(xtb + ((size_t)(ia & 0xffffu) << 8) + choff);
        g.p[1] = (const float4*)(xtb + ((size_t)(ia >> 16) << 8) + choff);
        g.p[2] = (const float4*)(xtb + ((size_t)(ib2 & 0xffffu) << 8) + choff);
        g.p[3] = (const float4*)(xtb + ((size_t)(ib2 >> 16) << 8) + choff);
        g.wq  = s_wq[e];
    };

    auto loadA = [&](uint32_t base, int h, uint32_t (*f)[4]) {
#pragma unroll
        for (int mi = 0; mi < 4; mi++)
            ldsm4(f[mi], base + a_off + (uint32_t)((mw * 64 + mi * 16) * 80 + h * 32));
    };
    auto loadB = [&](uint32_t base, int h, uint32_t (*f)[4]) {
#pragma unroll
        for (int p = 0; p < 2; p++)
            ldsm4(f[p], base + b_off + (uint32_t)((nw * 32 + p * 16) * 80 + h * 32));
    };
    auto mma_block = [&](uint32_t (*af)[4], uint32_t (*bf)[4]) {
#pragma unroll
        for (int mi = 0; mi < 4; mi++)
#pragma unroll
            for (int p = 0; p < 2; p++) {
                mma_bf16(acc[mi][2 * p],     af[mi], &bf[p][0]);
                mma_bf16(acc[mi][2 * p + 1], af[mi], &bf[p][2]);
            }
    };

    const uint32_t bstore = (uint32_t)(pxl * 80 + oct * 16);

    // ---- prologue ----
    {
        const float4* srcA0 = g_wA;
        uint32_t dA0 = sb + SM_A;
#pragma unroll
        for (int r = 0; r < 5; r++)
            cp_async16(dA0 + (uint32_t)((t + (r << 9)) << 4), srcA0 + t + (r << 9));
        cp_commit();
        const float4* srcA1 = g_wA + 2560;
        uint32_t dA1 = sb + SM_A + 40960;
#pragma unroll
        for (int r = 0; r < 5; r++)
            cp_async16(dA1 + (uint32_t)((t + (r << 9)) << 4), srcA1 + t + (r << 9));
        cp_commit();

        __syncthreads();

        GatherCtx g; load_ctx(0, g);
        float v[8], r[8];
        gather_issue(g, 0, r); gather_acc0(g, r, v);
        gather_issue(g, 1, r); gather_acc(g.wq.y, r, v);
        gather_issue(g, 2, r); gather_acc(g.wq.z, r, v);
        gather_issue(g, 3, r); gather_acc(g.wq.w, r, v);
        uint32_t ph[4], pl[4];
        pack4(v, ph, pl);
        char* bh = smem + SM_B + bstore;
        *(float4*)bh           = *(float4*)ph;
        *(float4*)(bh + 10240) = *(float4*)pl;

        cp_wait1();
        __syncthreads();
    }

    int cb = 0;
    for (int c = 0; c < NCH; c++) {
        const int nb = (cb == 2) ? 0 : cb + 1;
        const int pb = (nb == 2) ? 0 : nb + 1;

        const uint32_t Ah0 = sb + SM_A + cb * 40960;
        const uint32_t Al0 = Ah0 + 20480;
        const uint32_t Bh0 = sb + SM_B + cb * 20480;
        const uint32_t Bl0 = Bh0 + 10240;

        const bool pf = (c + 1 < NCH);
        GatherCtx g;
        float v[8], r[8];
        if (pf) { load_ctx(c + 1, g); gather_issue(g, 0, r); }

        uint32_t afh[4][4], afl[4][4], bfh[2][4], bfl[2][4];

        // ---- h = 0: Ah,Bh -> AhBh; Bl -> AhBl; Al -> AlBh ----
        loadA(Ah0, 0, afh); loadB(Bh0, 0, bfh);
        mma_block(afh, bfh);
        if (pf) { gather_acc0(g, r, v); gather_issue(g, 1, r); }
        loadB(Bl0, 0, bfl);
        mma_block(afh, bfl);
        if (pf) { gather_acc(g.wq.y, r, v); gather_issue(g, 2, r); }
        loadA(Al0, 0, afl);
        mma_block(afl, bfh);
        if (pf) { gather_acc(g.wq.z, r, v); gather_issue(g, 3, r); }

        // ---- h = 1: same pattern ----
        loadA(Ah0, 1, afh); loadB(Bh0, 1, bfh);
        mma_block(afh, bfh);
        if (pf) {
            gather_acc(g.wq.w, r, v);
            uint32_t ph[4], pl[4];
            pack4(v, ph, pl);
            char* bh = smem + SM_B + nb * 20480 + bstore;
            *(float4*)bh           = *(float4*)ph;
            *(float4*)(bh + 10240) = *(float4*)pl;
        }
        if (c + 2 < NCH) {
            const float4* srcA = g_wA + (size_t)(c + 2) * 2560;
            uint32_t dA = sb + SM_A + pb * 40960;
#pragma unroll
            for (int rr = 0; rr < 5; rr++)
                cp_async16(dA + (uint32_t)((t + (rr << 9)) << 4), srcA + t + (rr << 9));
            cp_commit();
        }
        loadB(Bl0, 1, bfl);
        mma_block(afh, bfl);
        loadA(Al0, 1, afl);
        mma_block(afl, bfh);

        if (c + 2 < NCH) cp_wait1();
        else             cp_wait0();
        __syncthreads();
        cb = nb;
    }

    // ---- epilogue ----
    const int m0   = mw * 64 + (lane >> 2);
    const int col0 = nw * 32 + ((lane & 3) << 1);
#pragma unroll
    for (int mi = 0; mi < 4; mi++) {
        int o = m0 + mi * 16;
        float bv0 = __ldg(bias + o);
        float bv1 = __ldg(bias + o + 8);
        float* r0 = out + (((size_t)(b * O_ + o)) << 12) + pib;
        float* r1 = r0 + (8 << 12);
#pragma unroll
        for (int nj = 0; nj < 4; nj++) {
            int cc = col0 + nj * 8;
            float2 v0 = make_float2(acc[mi][nj][0] + bv0, acc[mi][nj][1] + bv0);
            float2 v1 = make_float2(acc[mi][nj][2] + bv1, acc[mi][nj][3] + bv1);
            *(float2*)(r0 + cc) = v0;
            *(float2*)(r1 + cc) = v1;
        }
    }
}

// ---------------------------------------------------------------------------
// Launch — om runs BEFORE prep_xt so its x reads stay warm in L2.
// ---------------------------------------------------------------------------
extern "C" void kernel_launch(void* const* d_in, const int* in_sizes, int n_in,
                              void* d_out, int out_size)
{
    const float* x      = (const float*)d_in[0];
    const float* w_off  = (const float*)d_in[1];
    const float* b_off  = (const float*)d_in[2];
    const float* weight = (const float*)d_in[3];
    const float* bias   = (const float*)d_in[4];
    float* out = (float*)d_out;

    cudaFuncSetAttribute(dcn_mma_kernel,
                         cudaFuncAttributeMaxDynamicSharedMemorySize, DYN_SMEM);
    cudaFuncSetAttribute(om_mma_kernel,
                         cudaFuncAttributeMaxDynamicSharedMemorySize, OM_SMEM);

    prep_w_kernel<<<2304, 256>>>(weight);
    prep_woff_kernel<<<288, 256>>>(w_off);
    om_mma_kernel<<<128, 256, OM_SMEM>>>(x, b_off);
    prep_xt_kernel<<<dim3(128, 8, 4), 256>>>(x);
    dcn_mma_kernel<<<NPIX / 128, 512, DYN_SMEM>>>(x, bias, out);
}